// round 4
// baseline (speedup 1.0000x reference)
#include <cuda_runtime.h>
#include <cuda_bf16.h>
#include <math.h>
#include <stdint.h>

// Problem shapes (fixed)
#define BDIM 32
#define SDIM 2048
#define HDIM 512
#define EDIM 512
#define ROWS (BDIM * SDIM)   // 65536

// Scratch (device globals: allocation-free rule)
__device__ float g_w[ROWS];
__device__ float g_denInv[ROWS];
__device__ float g_gbuf[(size_t)ROWS * EDIM];      // 128 MB: w*tanh(XWb^T)*embed
__device__ float g_csums[BDIM * 16 * EDIM];        // chunk sums for 2-pass scan

// ======================= helpers =======================
__device__ __forceinline__ uint32_t smem_u32(const void* p) {
    uint32_t a;
    asm("{ .reg .u64 t; cvta.to.shared.u64 t, %1; cvt.u32.u64 %0, t; }" : "=r"(a) : "l"(p));
    return a;
}
__device__ __forceinline__ void cp16(void* sdst, const void* gsrc) {
    uint32_t d = smem_u32(sdst);
    asm volatile("cp.async.cg.shared.global [%0], [%1], 16;" :: "r"(d), "l"(gsrc) : "memory");
}
#define CP_COMMIT() asm volatile("cp.async.commit_group;" ::: "memory")
#define CP_WAIT(n)  asm volatile("cp.async.wait_group %0;" :: "n"(n) : "memory")

__device__ __forceinline__ uint32_t f2tf32(float f) {
    uint32_t o;
    asm("cvt.rna.tf32.f32 %0, %1;" : "=r"(o) : "f"(f));
    return o;
}
__device__ __forceinline__ void mma_tf32(float* c, const uint32_t* a, const uint32_t* b) {
    asm volatile(
        "mma.sync.aligned.m16n8k8.row.col.f32.tf32.tf32.f32 "
        "{%0,%1,%2,%3}, {%4,%5,%6,%7}, {%8,%9}, {%0,%1,%2,%3};"
        : "+f"(c[0]), "+f"(c[1]), "+f"(c[2]), "+f"(c[3])
        : "r"(a[0]), "r"(a[1]), "r"(a[2]), "r"(a[3]), "r"(b[0]), "r"(b[1]));
}

// ======================= Kernel 1: w = exp(alpha . Wa + ba) =======================
__global__ void RA_w_kernel(const float* __restrict__ alpha, const float* __restrict__ Wa,
                            const float* __restrict__ ba) {
    __shared__ __align__(16) float sWa[HDIM];
    int tid = threadIdx.x;
    for (int i = tid; i < HDIM; i += blockDim.x) sWa[i] = Wa[i];
    __syncthreads();
    int wid = tid >> 5, lane = tid & 31;
    int row = blockIdx.x * 8 + wid;
    const float4* a4 = (const float4*)(alpha + (size_t)row * HDIM);
    const float4* w4 = (const float4*)sWa;
    float sum = 0.f;
#pragma unroll
    for (int i = 0; i < 4; i++) {
        float4 a = a4[lane + i * 32];
        float4 w = w4[lane + i * 32];
        sum += a.x * w.x + a.y * w.y + a.z * w.z + a.w * w.w;
    }
#pragma unroll
    for (int o = 16; o > 0; o >>= 1) sum += __shfl_xor_sync(0xffffffffu, sum, o);
    if (lane == 0) g_w[row] = expf(sum + ba[0]);
}

// ======================= Kernel 2: denInv = 1/(cumsum(w)+1e-10), per b =======================
__global__ void RA_den_kernel() {
    int b = blockIdx.x, lane = threadIdx.x;
    const float* wb = g_w + b * SDIM;
    float* di = g_denInv + b * SDIM;
    float carry = 0.f;
    for (int c = 0; c < SDIM / 32; c++) {
        float v = wb[c * 32 + lane];
#pragma unroll
        for (int o = 1; o < 32; o <<= 1) {
            float t = __shfl_up_sync(0xffffffffu, v, o);
            if (lane >= o) v += t;
        }
        v += carry;
        di[c * 32 + lane] = 1.0f / (v + 1e-10f);
        carry = __shfl_sync(0xffffffffu, v, 31);
    }
}

// ======================= Kernel 3: tf32 mma.sync GEMM + fused epilogue =======================
// g[row, e] = w[row] * tanh( X[row,:] . Wb[e,:] + bb[e] ) * embed[row, e]
#define MT 128
#define NT 256
#define KB 32
#define KT (HDIM / KB)   // 16 k-tiles
#define NSTAGE 3
#define LDA 36           // KB + 4 pad (floats); 144B rows, 16B-aligned, conflict-free frags
#define A_ST_FL (MT * LDA)           // 4608 floats
#define B_ST_FL (NT * LDA)           // 9216 floats
#define ST_FL (A_ST_FL + B_ST_FL)    // 13824 floats per stage
#define GEMM_SMEM_FL (NSTAGE * ST_FL + NT)   // + bb tile
#define GEMM_SMEM (GEMM_SMEM_FL * 4)         // 166912 bytes

__device__ __forceinline__ void gemm_load_stage(float* smem, int s, int kt,
                                                const float* __restrict__ A,
                                                const float* __restrict__ B,
                                                int m0, int n0, int tid) {
    float* sA = smem + s * ST_FL;
    float* sB = sA + A_ST_FL;
    // A: MT x KB -> MT*KB/4 = 1024 float4 chunks; 256 threads -> 4 each
#pragma unroll
    for (int i = 0; i < 4; i++) {
        int id = tid + i * 256;
        int r = id >> 3, c4 = id & 7;
        cp16(sA + r * LDA + c4 * 4, A + (size_t)(m0 + r) * HDIM + kt * KB + c4 * 4);
    }
    // B: NT x KB -> 2048 chunks; 8 each
#pragma unroll
    for (int i = 0; i < 8; i++) {
        int id = tid + i * 256;
        int r = id >> 3, c4 = id & 7;
        cp16(sB + r * LDA + c4 * 4, B + (size_t)(n0 + r) * HDIM + kt * KB + c4 * 4);
    }
}

__global__ void __launch_bounds__(256, 1) RA_gemm_kernel(
    const float* __restrict__ Abeta,   // [ROWS, HDIM]
    const float* __restrict__ Wb,      // [EDIM, HDIM]
    const float* __restrict__ bb,      // [EDIM]
    const float* __restrict__ embed)   // [ROWS, EDIM]
{
    extern __shared__ float smem[];
    int tid = threadIdx.x, wid = tid >> 5, lane = tid & 31;
    int g = lane >> 2, tg = lane & 3;
    int n0 = blockIdx.x * NT, m0 = blockIdx.y * MT;
    int wm = wid & 1, wn = wid >> 1;   // 2 x 4 warp grid; warp tile 64(M) x 64(N)

    float* sBB = smem + NSTAGE * ST_FL;
    if (tid < NT) sBB[tid] = bb[n0 + tid];

    // prologue: stages 0..NSTAGE-2
#pragma unroll
    for (int s = 0; s < NSTAGE - 1; s++) {
        gemm_load_stage(smem, s, s, Abeta, Wb, m0, n0, tid);
        CP_COMMIT();
    }

    float acc[4][8][4];
#pragma unroll
    for (int i = 0; i < 4; i++)
#pragma unroll
        for (int j = 0; j < 8; j++)
#pragma unroll
            for (int q = 0; q < 4; q++) acc[i][j][q] = 0.f;

    for (int kt = 0; kt < KT; kt++) {
        CP_WAIT(NSTAGE - 2);
        __syncthreads();
        int buf = kt % NSTAGE;
        const float* sA = smem + buf * ST_FL + (wm * 64 + g) * LDA + tg;
        const float* sB = smem + buf * ST_FL + A_ST_FL + (wn * 64 + g) * LDA + tg;
#pragma unroll
        for (int k8 = 0; k8 < KB / 8; k8++) {
            const float* pA = sA + k8 * 8;
            const float* pB = sB + k8 * 8;
            uint32_t a[4][4];
#pragma unroll
            for (int i = 0; i < 4; i++) {
                a[i][0] = f2tf32(pA[(i * 16 + 0) * LDA + 0]);
                a[i][1] = f2tf32(pA[(i * 16 + 8) * LDA + 0]);
                a[i][2] = f2tf32(pA[(i * 16 + 0) * LDA + 4]);
                a[i][3] = f2tf32(pA[(i * 16 + 8) * LDA + 4]);
            }
#pragma unroll
            for (int j = 0; j < 8; j++) {
                uint32_t b[2];
                b[0] = f2tf32(pB[j * 8 * LDA + 0]);
                b[1] = f2tf32(pB[j * 8 * LDA + 4]);
#pragma unroll
                for (int i = 0; i < 4; i++) mma_tf32(acc[i][j], a[i], b);
            }
        }
        // issue next stage (buffer (kt+NSTAGE-1)%NSTAGE was drained in iter kt-1;
        // the syncthreads above makes its reuse safe)
        if (kt + NSTAGE - 1 < KT)
            gemm_load_stage(smem, (kt + NSTAGE - 1) % NSTAGE, kt + NSTAGE - 1,
                            Abeta, Wb, m0, n0, tid);
        CP_COMMIT();
    }

    // epilogue: bias + tanh + w*embed -> g_gbuf
    int m_base = m0 + wm * 64, n_base = n0 + wn * 64;
#pragma unroll
    for (int i = 0; i < 4; i++) {
#pragma unroll
        for (int r2 = 0; r2 < 2; r2++) {
            int row = m_base + i * 16 + g + r2 * 8;
            float wr = g_w[row];
            const float* erow = embed + (size_t)row * EDIM;
            float* orow = g_gbuf + (size_t)row * EDIM;
#pragma unroll
            for (int j = 0; j < 8; j++) {
                int nc = n_base + j * 8 + tg * 2;
                float2 ee = *(const float2*)(erow + nc);
                float b0 = sBB[nc - n0], b1 = sBB[nc - n0 + 1];
                float2 r;
                r.x = wr * tanhf(acc[i][j][r2 * 2 + 0] + b0) * ee.x;
                r.y = wr * tanhf(acc[i][j][r2 * 2 + 1] + b1) * ee.y;
                *(float2*)(orow + nc) = r;
            }
        }
    }
}

// ======================= Kernel 4: per-chunk column sums (chunk = 128 s-steps) =======================
__global__ void RA_csum_kernel() {
    int b = blockIdx.x >> 4, c = blockIdx.x & 15;
    int e = threadIdx.x * 4;
    const float4* g = (const float4*)(g_gbuf + ((size_t)(b * SDIM + c * 128)) * EDIM + e);
    float4 s = make_float4(0.f, 0.f, 0.f, 0.f);
#pragma unroll 4
    for (int i = 0; i < 128; i++) {
        float4 v = g[(size_t)i * (EDIM / 4)];
        s.x += v.x; s.y += v.y; s.z += v.z; s.w += v.w;
    }
    *(float4*)(g_csums + (size_t)blockIdx.x * EDIM + e) = s;
}

// ======================= Kernel 5: chunked scan + divide =======================
__global__ void RA_scan_kernel(float* __restrict__ out) {
    __shared__ float sdi[128];
    int b = blockIdx.x >> 4, c = blockIdx.x & 15;
    int e = threadIdx.x * 4;
    sdi[threadIdx.x] = g_denInv[b * SDIM + c * 128 + threadIdx.x];
    float4 acc = make_float4(0.f, 0.f, 0.f, 0.f);
    for (int cp = 0; cp < c; cp++) {
        float4 v = *(const float4*)(g_csums + (size_t)(b * 16 + cp) * EDIM + e);
        acc.x += v.x; acc.y += v.y; acc.z += v.z; acc.w += v.w;
    }
    __syncthreads();
    size_t base = ((size_t)(b * SDIM + c * 128)) * EDIM + e;
    const float4* g = (const float4*)(g_gbuf + base);
    float4* o = (float4*)(out + base);
#pragma unroll 4
    for (int i = 0; i < 128; i++) {
        float4 v = g[(size_t)i * (EDIM / 4)];
        acc.x += v.x; acc.y += v.y; acc.z += v.z; acc.w += v.w;
        float di = sdi[i];
        o[(size_t)i * (EDIM / 4)] = make_float4(acc.x * di, acc.y * di, acc.z * di, acc.w * di);
    }
}

// ======================= Host launch =======================
extern "C" void kernel_launch(void* const* d_in, const int* in_sizes, int n_in,
                              void* d_out, int out_size) {
    const float* alpha   = (const float*)d_in[0];
    const float* beta_in = (const float*)d_in[1];
    const float* embed   = (const float*)d_in[2];
    const float* Wb      = (const float*)d_in[3];
    const float* bb      = (const float*)d_in[4];
    const float* Wa      = (const float*)d_in[5];
    const float* ba      = (const float*)d_in[6];
    float* out = (float*)d_out;

    RA_w_kernel<<<ROWS / 8, 256>>>(alpha, Wa, ba);
    RA_den_kernel<<<BDIM, 32>>>();
    cudaFuncSetAttribute(RA_gemm_kernel, cudaFuncAttributeMaxDynamicSharedMemorySize, GEMM_SMEM);
    RA_gemm_kernel<<<dim3(EDIM / NT, ROWS / MT), 256, GEMM_SMEM>>>(beta_in, Wb, bb, embed);
    RA_csum_kernel<<<BDIM * 16, 128>>>();
    RA_scan_kernel<<<BDIM * 16, 128>>>(out);
    (void)in_sizes; (void)n_in; (void)out_size;
}

// round 5
// speedup vs baseline: 1.2361x; 1.2361x over previous
#include <cuda_runtime.h>
#include <cuda_bf16.h>
#include <math.h>
#include <stdint.h>

// Problem shapes (fixed)
#define BDIM 32
#define SDIM 2048
#define HDIM 512
#define EDIM 512
#define ROWS (BDIM * SDIM)   // 65536
#define NCHUNK 32            // 64-row scan chunks per batch
#define CHROWS 64

// Scratch (device globals: allocation-free rule)
__device__ float g_w[ROWS];
__device__ float g_denInv[ROWS];
__device__ float g_gbuf[(size_t)ROWS * EDIM];          // 128 MB: w*tanh(XWb^T)*embed
__device__ float g_csums[(size_t)(ROWS / CHROWS) * EDIM]; // 1024 x 512 chunk sums

// ======================= helpers =======================
__device__ __forceinline__ uint32_t smem_u32(const void* p) {
    uint32_t a;
    asm("{ .reg .u64 t; cvta.to.shared.u64 t, %1; cvt.u32.u64 %0, t; }" : "=r"(a) : "l"(p));
    return a;
}
__device__ __forceinline__ void cp16(void* sdst, const void* gsrc) {
    uint32_t d = smem_u32(sdst);
    asm volatile("cp.async.cg.shared.global [%0], [%1], 16;" :: "r"(d), "l"(gsrc) : "memory");
}
#define CP_COMMIT() asm volatile("cp.async.commit_group;" ::: "memory")
#define CP_WAIT(n)  asm volatile("cp.async.wait_group %0;" :: "n"(n) : "memory")

__device__ __forceinline__ uint32_t f2tf32(float f) {
    uint32_t o;
    asm("cvt.rna.tf32.f32 %0, %1;" : "=r"(o) : "f"(f));
    return o;
}
__device__ __forceinline__ void mma_tf32(float* c, const uint32_t* a, const uint32_t* b) {
    asm volatile(
        "mma.sync.aligned.m16n8k8.row.col.f32.tf32.tf32.f32 "
        "{%0,%1,%2,%3}, {%4,%5,%6,%7}, {%8,%9}, {%0,%1,%2,%3};"
        : "+f"(c[0]), "+f"(c[1]), "+f"(c[2]), "+f"(c[3])
        : "r"(a[0]), "r"(a[1]), "r"(a[2]), "r"(a[3]), "r"(b[0]), "r"(b[1]));
}

// ======================= Kernel 1: w = exp(alpha . Wa + ba) =======================
__global__ void RA_w_kernel(const float* __restrict__ alpha, const float* __restrict__ Wa,
                            const float* __restrict__ ba) {
    __shared__ __align__(16) float sWa[HDIM];
    int tid = threadIdx.x;
    for (int i = tid; i < HDIM; i += blockDim.x) sWa[i] = Wa[i];
    __syncthreads();
    int wid = tid >> 5, lane = tid & 31;
    int row = blockIdx.x * 8 + wid;
    const float4* a4 = (const float4*)(alpha + (size_t)row * HDIM);
    const float4* w4 = (const float4*)sWa;
    float sum = 0.f;
#pragma unroll
    for (int i = 0; i < 4; i++) {
        float4 a = a4[lane + i * 32];
        float4 w = w4[lane + i * 32];
        sum += a.x * w.x + a.y * w.y + a.z * w.z + a.w * w.w;
    }
#pragma unroll
    for (int o = 16; o > 0; o >>= 1) sum += __shfl_xor_sync(0xffffffffu, sum, o);
    if (lane == 0) g_w[row] = expf(sum + ba[0]);
}

// ======================= Kernel 2: denInv = 1/(cumsum(w)+1e-10), per b =======================
// smem-staged: coalesced load, per-lane 64-chunk serial scan in smem,
// warp scan of chunk totals, broadcast exclusive offsets, coalesced store.
__global__ void RA_den_kernel() {
    __shared__ float sw[SDIM];
    __shared__ float sx[32];
    int b = blockIdx.x, tid = threadIdx.x;
    for (int i = tid; i < SDIM; i += 256) sw[i] = g_w[b * SDIM + i];
    __syncthreads();
    if (tid < 32) {
        int lane = tid;
        int base = lane * 64;
        float s = 0.f;
        for (int i = 0; i < 64; i++) { s += sw[base + i]; sw[base + i] = s; }
        float tot = s;
#pragma unroll
        for (int o = 1; o < 32; o <<= 1) {
            float t = __shfl_up_sync(0xffffffffu, tot, o);
            if (lane >= o) tot += t;
        }
        sx[lane] = tot - s;   // exclusive prefix of chunk totals
    }
    __syncthreads();
    float* di = g_denInv + b * SDIM;
    for (int i = tid; i < SDIM; i += 256)
        di[i] = 1.0f / (sw[i] + sx[i >> 6] + 1e-10f);
}

// ======================= Kernel 3: tf32 mma.sync GEMM + fused epilogue + chunk sums =======================
// g[row, e] = w[row] * tanh( X[row,:] . Wb[e,:] + bb[e] ) * embed[row, e]
// also writes g_csums[row/64][e] = sum over the 64-row chunk.
#define MT 128
#define NT 256
#define KB 32
#define KT (HDIM / KB)   // 16 k-tiles
#define NSTAGE 3
#define LDA 36           // KB + 4 pad (floats); conflict-free frags
#define A_ST_FL (MT * LDA)
#define B_ST_FL (NT * LDA)
#define ST_FL (A_ST_FL + B_ST_FL)
#define GEMM_SMEM_FL (NSTAGE * ST_FL + NT)
#define GEMM_SMEM (GEMM_SMEM_FL * 4)   // 166912 bytes

__device__ __forceinline__ void gemm_load_stage(float* smem, int s, int kt,
                                                const float* __restrict__ A,
                                                const float* __restrict__ B,
                                                int m0, int n0, int tid) {
    float* sA = smem + s * ST_FL;
    float* sB = sA + A_ST_FL;
#pragma unroll
    for (int i = 0; i < 4; i++) {
        int id = tid + i * 256;
        int r = id >> 3, c4 = id & 7;
        cp16(sA + r * LDA + c4 * 4, A + (size_t)(m0 + r) * HDIM + kt * KB + c4 * 4);
    }
#pragma unroll
    for (int i = 0; i < 8; i++) {
        int id = tid + i * 256;
        int r = id >> 3, c4 = id & 7;
        cp16(sB + r * LDA + c4 * 4, B + (size_t)(n0 + r) * HDIM + kt * KB + c4 * 4);
    }
}

__global__ void __launch_bounds__(256, 1) RA_gemm_kernel(
    const float* __restrict__ Abeta,   // [ROWS, HDIM]
    const float* __restrict__ Wb,      // [EDIM, HDIM]
    const float* __restrict__ bb,      // [EDIM]
    const float* __restrict__ embed)   // [ROWS, EDIM]
{
    extern __shared__ float smem[];
    int tid = threadIdx.x, wid = tid >> 5, lane = tid & 31;
    int g = lane >> 2, tg = lane & 3;
    int n0 = blockIdx.x * NT, m0 = blockIdx.y * MT;
    int wm = wid & 1, wn = wid >> 1;   // 2 x 4 warp grid; warp tile 64(M) x 64(N)

    float* sBB = smem + NSTAGE * ST_FL;
    if (tid < NT) sBB[tid] = bb[n0 + tid];

#pragma unroll
    for (int s = 0; s < NSTAGE - 1; s++) {
        gemm_load_stage(smem, s, s, Abeta, Wb, m0, n0, tid);
        CP_COMMIT();
    }

    float acc[4][8][4];
#pragma unroll
    for (int i = 0; i < 4; i++)
#pragma unroll
        for (int j = 0; j < 8; j++)
#pragma unroll
            for (int q = 0; q < 4; q++) acc[i][j][q] = 0.f;

    for (int kt = 0; kt < KT; kt++) {
        CP_WAIT(NSTAGE - 2);
        __syncthreads();
        // issue next stage EARLY so it overlaps the MMA loop below
        if (kt + NSTAGE - 1 < KT)
            gemm_load_stage(smem, (kt + NSTAGE - 1) % NSTAGE, kt + NSTAGE - 1,
                            Abeta, Wb, m0, n0, tid);
        CP_COMMIT();

        int buf = kt % NSTAGE;
        const float* sA = smem + buf * ST_FL + (wm * 64 + g) * LDA + tg;
        const float* sB = smem + buf * ST_FL + A_ST_FL + (wn * 64 + g) * LDA + tg;
#pragma unroll
        for (int k8 = 0; k8 < KB / 8; k8++) {
            const float* pA = sA + k8 * 8;
            const float* pB = sB + k8 * 8;
            uint32_t a[4][4];
#pragma unroll
            for (int i = 0; i < 4; i++) {
                a[i][0] = f2tf32(pA[(i * 16 + 0) * LDA + 0]);
                a[i][1] = f2tf32(pA[(i * 16 + 8) * LDA + 0]);
                a[i][2] = f2tf32(pA[(i * 16 + 0) * LDA + 4]);
                a[i][3] = f2tf32(pA[(i * 16 + 8) * LDA + 4]);
            }
#pragma unroll
            for (int j = 0; j < 8; j++) {
                uint32_t b[2];
                b[0] = f2tf32(pB[j * 8 * LDA + 0]);
                b[1] = f2tf32(pB[j * 8 * LDA + 4]);
#pragma unroll
                for (int i = 0; i < 4; i++) mma_tf32(acc[i][j], a[i], b);
            }
        }
    }

    // epilogue: bias + tanh + w*embed -> g_gbuf, plus fused 64-row chunk column sums
    int m_base = m0 + wm * 64, n_base = n0 + wn * 64;
    float cs[8][2];
#pragma unroll
    for (int j = 0; j < 8; j++) { cs[j][0] = 0.f; cs[j][1] = 0.f; }

#pragma unroll
    for (int i = 0; i < 4; i++) {
#pragma unroll
        for (int r2 = 0; r2 < 2; r2++) {
            int row = m_base + i * 16 + g + r2 * 8;
            float wr = g_w[row];
            const float* erow = embed + (size_t)row * EDIM;
            float* orow = g_gbuf + (size_t)row * EDIM;
#pragma unroll
            for (int j = 0; j < 8; j++) {
                int nc = n_base + j * 8 + tg * 2;
                float2 ee = *(const float2*)(erow + nc);
                float b0 = sBB[nc - n0], b1 = sBB[nc - n0 + 1];
                float2 r;
                r.x = wr * tanhf(acc[i][j][r2 * 2 + 0] + b0) * ee.x;
                r.y = wr * tanhf(acc[i][j][r2 * 2 + 1] + b1) * ee.y;
                *(float2*)(orow + nc) = r;
                cs[j][0] += r.x;
                cs[j][1] += r.y;
            }
        }
    }
    // reduce over the 8 g-lanes (lane bits 2..4) -> full 64-row column sums
#pragma unroll
    for (int j = 0; j < 8; j++) {
#pragma unroll
        for (int q = 0; q < 2; q++) {
            float v = cs[j][q];
            v += __shfl_xor_sync(0xffffffffu, v, 4);
            v += __shfl_xor_sync(0xffffffffu, v, 8);
            v += __shfl_xor_sync(0xffffffffu, v, 16);
            cs[j][q] = v;
        }
    }
    if (g == 0) {   // lanes 0..3, unique (chunk, col) writers
        int chunk = (m_base >> 6);   // global 64-row chunk id
        float* crow = g_csums + (size_t)chunk * EDIM;
#pragma unroll
        for (int j = 0; j < 8; j++) {
            int col = n_base + j * 8 + tg * 2;
            crow[col] = cs[j][0];
            crow[col + 1] = cs[j][1];
        }
    }
}

// ======================= Kernel 4: chunked scan + divide (chunk = 64 rows) =======================
__global__ void __launch_bounds__(128) RA_scan_kernel(float* __restrict__ out) {
    __shared__ float sdi[CHROWS];
    int b = blockIdx.x >> 5, c = blockIdx.x & 31;
    int e = threadIdx.x * 4;
    if (threadIdx.x < CHROWS)
        sdi[threadIdx.x] = g_denInv[b * SDIM + c * CHROWS + threadIdx.x];

    float4 acc = make_float4(0.f, 0.f, 0.f, 0.f);
    {
        const float4* cbase = (const float4*)(g_csums + (size_t)(b * NCHUNK) * EDIM + e);
        for (int cp = 0; cp < c; cp++) {
            float4 v = cbase[(size_t)cp * (EDIM / 4)];
            acc.x += v.x; acc.y += v.y; acc.z += v.z; acc.w += v.w;
        }
    }
    __syncthreads();
    size_t base = ((size_t)(b * SDIM + c * CHROWS)) * EDIM + e;
    const float4* gb = (const float4*)(g_gbuf + base);
    float4* o = (float4*)(out + base);
    for (int ii = 0; ii < CHROWS; ii += 8) {
        float4 v[8];
#pragma unroll
        for (int k = 0; k < 8; k++) v[k] = gb[(size_t)(ii + k) * (EDIM / 4)];
#pragma unroll
        for (int k = 0; k < 8; k++) {
            acc.x += v[k].x; acc.y += v[k].y; acc.z += v[k].z; acc.w += v[k].w;
            float di = sdi[ii + k];
            o[(size_t)(ii + k) * (EDIM / 4)] =
                make_float4(acc.x * di, acc.y * di, acc.z * di, acc.w * di);
        }
    }
}

// ======================= Host launch =======================
extern "C" void kernel_launch(void* const* d_in, const int* in_sizes, int n_in,
                              void* d_out, int out_size) {
    const float* alpha   = (const float*)d_in[0];
    const float* beta_in = (const float*)d_in[1];
    const float* embed   = (const float*)d_in[2];
    const float* Wb      = (const float*)d_in[3];
    const float* bb      = (const float*)d_in[4];
    const float* Wa      = (const float*)d_in[5];
    const float* ba      = (const float*)d_in[6];
    float* out = (float*)d_out;

    RA_w_kernel<<<ROWS / 8, 256>>>(alpha, Wa, ba);
    RA_den_kernel<<<BDIM, 256>>>();
    cudaFuncSetAttribute(RA_gemm_kernel, cudaFuncAttributeMaxDynamicSharedMemorySize, GEMM_SMEM);
    RA_gemm_kernel<<<dim3(EDIM / NT, ROWS / MT), 256, GEMM_SMEM>>>(beta_in, Wb, bb, embed);
    RA_scan_kernel<<<BDIM * NCHUNK, 128>>>(out);
    (void)in_sizes; (void)n_in; (void)out_size;
}